// round 2
// baseline (speedup 1.0000x reference)
#include <cuda_runtime.h>
#include <cstdint>

#define E_DIM   8192
#define N_NODES 2048
#define B_SZ    16
#define DIMV    64
#define DH      32
#define NCOL    512      // B_SZ * DH
#define SPLITK  8
#define MT      128
#define NT      256
#define KS      16
#define NSTAGE  64       // (E_DIM/SPLITK)/KS
// smem float offsets
#define RAW_FLOATS_PER_STAGE 6144   // 3 arrays * 128*16
#define XE_OFF   24576              // 4 * 6144
#define XE_FLOATS_PER_STAGE 4224    // 16 * 264
#define XE_STRIDE 264
#define AC_OFF   41472              // XE_OFF + 4*4224
#define AC_FLOATS 2560              // 128 * 20
#define AC_STRIDE 20
#define SMEM_FLOATS (AC_OFF + 2*AC_FLOATS)   // 46592
#define SMEM_BYTES  (SMEM_FLOATS * 4)        // 186368

// scratch (allocation-free: __device__ globals)
__device__ float g_xe[(size_t)E_DIM * NCOL];                    // 16 MB, tf32-rounded
__device__ float g_part[(size_t)SPLITK * N_NODES * NCOL];       // 32 MB

__device__ __forceinline__ uint32_t f2tf(float x) {
    uint32_t u; asm("cvt.rna.tf32.f32 %0, %1;" : "=r"(u) : "f"(x)); return u;
}
__device__ __forceinline__ float f2tf_f(float x) { return __uint_as_float(f2tf(x)); }

__device__ __forceinline__ void cpa16(uint32_t saddr, const void* g) {
    asm volatile("cp.async.cg.shared.global [%0], [%1], 16;" :: "r"(saddr), "l"(g));
}
__device__ __forceinline__ void cp_commit() {
    asm volatile("cp.async.commit_group;" ::: "memory");
}
__device__ __forceinline__ void cp_wait2() {
    asm volatile("cp.async.wait_group 2;" ::: "memory");
}

__device__ __forceinline__ void mma_tf32(float& d0, float& d1, float& d2, float& d3,
                                         uint32_t a0, uint32_t a1, uint32_t a2, uint32_t a3,
                                         uint32_t b0, uint32_t b1) {
    asm volatile("mma.sync.aligned.m16n8k8.row.col.f32.tf32.tf32.f32 "
                 "{%0,%1,%2,%3},{%4,%5,%6,%7},{%8,%9},{%0,%1,%2,%3};"
                 : "+f"(d0), "+f"(d1), "+f"(d2), "+f"(d3)
                 : "r"(a0), "r"(a1), "r"(a2), "r"(a3), "r"(b0), "r"(b1));
}

// ---------------- kernel 1: xe = relu(inputs @ W + bias), stored [E][B*DH] tf32-rounded ----------------
__global__ __launch_bounds__(256) void xe_kernel(const float* __restrict__ inp,
                                                 const float* __restrict__ W,
                                                 const float* __restrict__ bias) {
    __shared__ float Ws[DIMV * DH];   // 8 KB
    int t = threadIdx.x;
#pragma unroll
    for (int k = 0; k < 8; k++) Ws[t + k * 256] = W[t + k * 256];
    __syncthreads();

    int e  = blockIdx.x * 2 + (t >> 7);
    int t2 = t & 127;
    int b  = t2 >> 3;
    int hq = (t2 & 7) << 2;

    const float4* inrow = reinterpret_cast<const float4*>(inp + ((size_t)b * E_DIM + e) * DIMV);
    float a0 = bias[hq], a1 = bias[hq + 1], a2 = bias[hq + 2], a3 = bias[hq + 3];
#pragma unroll
    for (int dd = 0; dd < 16; dd++) {
        float4 iv = inrow[dd];
        const float* wr = Ws + (dd * 4) * DH + hq;
        float4 w0 = *reinterpret_cast<const float4*>(wr);
        float4 w1 = *reinterpret_cast<const float4*>(wr + DH);
        float4 w2 = *reinterpret_cast<const float4*>(wr + 2 * DH);
        float4 w3 = *reinterpret_cast<const float4*>(wr + 3 * DH);
        a0 = fmaf(iv.x, w0.x, a0); a1 = fmaf(iv.x, w0.y, a1); a2 = fmaf(iv.x, w0.z, a2); a3 = fmaf(iv.x, w0.w, a3);
        a0 = fmaf(iv.y, w1.x, a0); a1 = fmaf(iv.y, w1.y, a1); a2 = fmaf(iv.y, w1.z, a2); a3 = fmaf(iv.y, w1.w, a3);
        a0 = fmaf(iv.z, w2.x, a0); a1 = fmaf(iv.z, w2.y, a1); a2 = fmaf(iv.z, w2.z, a2); a3 = fmaf(iv.z, w2.w, a3);
        a0 = fmaf(iv.w, w3.x, a0); a1 = fmaf(iv.w, w3.y, a1); a2 = fmaf(iv.w, w3.z, a2); a3 = fmaf(iv.w, w3.w, a3);
    }
    float4 o;
    o.x = f2tf_f(fmaxf(a0, 0.f));
    o.y = f2tf_f(fmaxf(a1, 0.f));
    o.z = f2tf_f(fmaxf(a2, 0.f));
    o.w = f2tf_f(fmaxf(a3, 0.f));
    *reinterpret_cast<float4*>(g_xe + (size_t)e * NCOL + b * DH + hq) = o;
}

// ---------------- kernel 2: fused A-build + TF32 GEMM, split-K partials ----------------
__device__ __forceinline__ void load_stage(uint32_t sbase, int slot, int kG,
                                           const float* wg, const float* ig, const float* bg,
                                           int mBase, int nBase, int t) {
#pragma unroll
    for (int j = 0; j < 2; j++) {
        int c = t + j * 256;
        int row = c >> 2, q = c & 3;
        size_t go = (size_t)(mBase + row) * E_DIM + kG + q * 4;
        uint32_t so = sbase + (uint32_t)(slot * RAW_FLOATS_PER_STAGE + c * 4) * 4u;
        cpa16(so,              wg + go);
        cpa16(so + 2048u * 4u, ig + go);
        cpa16(so + 4096u * 4u, bg + go);
    }
#pragma unroll
    for (int j = 0; j < 4; j++) {
        int c = t + j * 256;
        int row = c >> 6, cq = c & 63;
        cpa16(sbase + (uint32_t)(XE_OFF + slot * XE_FLOATS_PER_STAGE + row * XE_STRIDE + cq * 4) * 4u,
              g_xe + (size_t)(kG + row) * NCOL + nBase + cq * 4);
    }
}

// each thread converts exactly the raw bytes it cp.async'd itself -> no cross-thread sync needed
__device__ __forceinline__ void convert_stage(float* sm, int slot, int buf, int t) {
    const float* raw = sm + slot * RAW_FLOATS_PER_STAGE;
    uint32_t* ac = reinterpret_cast<uint32_t*>(sm + AC_OFF + buf * AC_FLOATS);
#pragma unroll
    for (int j = 0; j < 2; j++) {
        int c = t + j * 256;
        int row = c >> 2, q = c & 3;
        float4 wv = *reinterpret_cast<const float4*>(raw + c * 4);
        float4 iv = *reinterpret_cast<const float4*>(raw + 2048 + c * 4);
        float4 bv = *reinterpret_cast<const float4*>(raw + 4096 + c * 4);
        uint4 o;
        o.x = f2tf(fmaf(wv.x, iv.x, bv.x));
        o.y = f2tf(fmaf(wv.y, iv.y, bv.y));
        o.z = f2tf(fmaf(wv.z, iv.z, bv.z));
        o.w = f2tf(fmaf(wv.w, iv.w, bv.w));
        *reinterpret_cast<uint4*>(ac + row * AC_STRIDE + q * 4) = o;
    }
}

__global__ __launch_bounds__(256, 1) void gemm_kernel(const float* __restrict__ wg,
                                                      const float* __restrict__ ig,
                                                      const float* __restrict__ bg) {
    extern __shared__ float sm[];
    int t = threadIdx.x;
    int lane = t & 31, warp = t >> 5;
    int wm = warp >> 2, wn = warp & 3;
    int lq = lane & 3, lr = lane >> 2;
    int mBase = blockIdx.x * MT;
    int nBase = blockIdx.y * NT;
    int sk = blockIdx.z;
    int kBase = sk * (E_DIM / SPLITK);
    uint32_t sbase = (uint32_t)__cvta_generic_to_shared(sm);

    float acc[4][8][4];
#pragma unroll
    for (int mi = 0; mi < 4; mi++)
#pragma unroll
        for (int nj = 0; nj < 8; nj++)
#pragma unroll
            for (int v = 0; v < 4; v++) acc[mi][nj][v] = 0.f;

    // prologue: stages 0..2 in flight, convert stage 0
#pragma unroll
    for (int p = 0; p < 3; p++) {
        load_stage(sbase, p, kBase + p * KS, wg, ig, bg, mBase, nBase, t);
        cp_commit();
    }
    cp_wait2();
    convert_stage(sm, 0, 0, t);

    for (int s = 0; s < NSTAGE; s++) {
        __syncthreads();   // publishes convert(s) + Xe(s); frees Acomp[(s+1)&1] and Xe slot (s+3)&3
        if (s + 3 < NSTAGE)
            load_stage(sbase, (s + 3) & 3, kBase + (s + 3) * KS, wg, ig, bg, mBase, nBase, t);
        cp_commit();

        const uint32_t* Ac = reinterpret_cast<const uint32_t*>(sm + AC_OFF + (s & 1) * AC_FLOATS);
        const uint32_t* Xs = reinterpret_cast<const uint32_t*>(sm + XE_OFF + (s & 3) * XE_FLOATS_PER_STAGE);
#pragma unroll
        for (int kk = 0; kk < 16; kk += 8) {
            uint32_t af[4][4], bf[8][2];
#pragma unroll
            for (int mi = 0; mi < 4; mi++) {
                int r = wm * 64 + mi * 16 + lr;
                af[mi][0] = Ac[r * AC_STRIDE + kk + lq];
                af[mi][1] = Ac[(r + 8) * AC_STRIDE + kk + lq];
                af[mi][2] = Ac[r * AC_STRIDE + kk + 4 + lq];
                af[mi][3] = Ac[(r + 8) * AC_STRIDE + kk + 4 + lq];
            }
#pragma unroll
            for (int nj = 0; nj < 8; nj++) {
                int c = wn * 64 + nj * 8 + lr;
                bf[nj][0] = Xs[(kk + lq) * XE_STRIDE + c];
                bf[nj][1] = Xs[(kk + 4 + lq) * XE_STRIDE + c];
            }
#pragma unroll
            for (int mi = 0; mi < 4; mi++)
#pragma unroll
                for (int nj = 0; nj < 8; nj++)
                    mma_tf32(acc[mi][nj][0], acc[mi][nj][1], acc[mi][nj][2], acc[mi][nj][3],
                             af[mi][0], af[mi][1], af[mi][2], af[mi][3],
                             bf[nj][0], bf[nj][1]);
        }
        if (s + 1 < NSTAGE) {
            cp_wait2();                       // own raw(s+1) visible to self
            convert_stage(sm, (s + 1) & 3, (s + 1) & 1, t);
        }
    }

    // epilogue: write split-K partials
#pragma unroll
    for (int mi = 0; mi < 4; mi++)
#pragma unroll
        for (int nj = 0; nj < 8; nj++) {
            int row = mBase + wm * 64 + mi * 16 + lr;
            int col = nBase + wn * 64 + nj * 8 + 2 * lq;
            float* p = g_part + ((size_t)sk * N_NODES + row) * NCOL + col;
            *reinterpret_cast<float2*>(p) = make_float2(acc[mi][nj][0], acc[mi][nj][1]);
            *reinterpret_cast<float2*>(p + 8 * NCOL) = make_float2(acc[mi][nj][2], acc[mi][nj][3]);
        }
}

// ---------------- kernel 3: reduce split-K partials -> out[b,n,h] ----------------
__global__ __launch_bounds__(256) void reduce_kernel(float* __restrict__ out) {
    int i = blockIdx.x * 256 + threadIdx.x;   // 0 .. 262143
    int base = i * 4;
    int n = base >> 9;
    int c = base & 511;
    float4 a = make_float4(0.f, 0.f, 0.f, 0.f);
#pragma unroll
    for (int s = 0; s < SPLITK; s++) {
        float4 v = *reinterpret_cast<const float4*>(g_part + ((size_t)s * N_NODES + n) * NCOL + c);
        a.x += v.x; a.y += v.y; a.z += v.z; a.w += v.w;
    }
    int b = c >> 5, h = c & 31;
    *reinterpret_cast<float4*>(out + ((size_t)b * N_NODES + n) * DH + h) = a;
}

extern "C" void kernel_launch(void* const* d_in, const int* in_sizes, int n_in,
                              void* d_out, int out_size) {
    const float* inp  = (const float*)d_in[0];
    const float* W    = (const float*)d_in[1];
    const float* bias = (const float*)d_in[2];
    const float* inci = (const float*)d_in[3];
    const float* w    = (const float*)d_in[4];
    const float* b    = (const float*)d_in[5];
    float* out = (float*)d_out;

    cudaFuncSetAttribute(gemm_kernel, cudaFuncAttributeMaxDynamicSharedMemorySize, SMEM_BYTES);

    xe_kernel<<<E_DIM / 2, 256>>>(inp, W, bias);
    dim3 grid(N_NODES / MT, NCOL / NT, SPLITK);   // (16, 2, 8)
    gemm_kernel<<<grid, 256, SMEM_BYTES>>>(w, inci, b);
    reduce_kernel<<<(N_NODES * NCOL) / (4 * 256), 256>>>(out);
}

// round 4
// speedup vs baseline: 1.2685x; 1.2685x over previous
#include <cuda_runtime.h>
#include <cuda_fp16.h>
#include <cstdint>

#define E_DIM   8192
#define N_NODES 2048
#define NCOL    512      // B*DH = 16*32
#define MT      128
#define NT      256
#define SPLITK  4
#define KSLICE  2048     // E_DIM / SPLITK
#define KC      32       // k per stage
#define NSTG    64       // KSLICE / KC

// ---- gemm smem: 3 stages x (A 128x80B + B 256x80B) ----
#define A_ROWB  80
#define STG_A   0
#define STG_B   10240            // 128*80
#define STG_BYTES 30720          // 10240 + 256*80
#define GEMM_SMEM (3*STG_BYTES)  // 92160

// ---- xe smem (floats) ----
#define XE_TS_OFF 16384
#define XE_SMEM   ((16384 + 8*32*33) * 4)   // 99328 bytes

// scratch (__device__ globals; no allocation)
__device__ __align__(16) __half g_xeh[(size_t)NCOL * E_DIM];     // 8 MB  [c][e]
__device__ __align__(16) __half g_ah [(size_t)N_NODES * E_DIM];  // 32 MB [m][k]
__device__ float g_part[(size_t)SPLITK * N_NODES * NCOL];        // 16 MB

// ============================ helpers ============================
__device__ __forceinline__ uint32_t smem_u32(const void* p) {
    uint32_t a; asm("{ .reg .u64 t; cvta.to.shared.u64 t, %1; cvt.u32.u64 %0, t; }" : "=r"(a) : "l"(p));
    return a;
}
__device__ __forceinline__ void cpa16(uint32_t saddr, const void* g) {
    asm volatile("cp.async.cg.shared.global [%0], [%1], 16;" :: "r"(saddr), "l"(g));
}
#define CP_COMMIT() asm volatile("cp.async.commit_group;" ::: "memory")
#define CP_WAIT(n)  asm volatile("cp.async.wait_group %0;" :: "n"(n) : "memory")

__device__ __forceinline__ void ldmx4(uint32_t& r0, uint32_t& r1, uint32_t& r2, uint32_t& r3,
                                      uint32_t addr) {
    asm volatile("ldmatrix.sync.aligned.m8n8.x4.shared.b16 {%0,%1,%2,%3}, [%4];"
                 : "=r"(r0), "=r"(r1), "=r"(r2), "=r"(r3) : "r"(addr));
}
__device__ __forceinline__ void mma16816(float& d0, float& d1, float& d2, float& d3,
                                         uint32_t a0, uint32_t a1, uint32_t a2, uint32_t a3,
                                         uint32_t b0, uint32_t b1) {
    asm volatile("mma.sync.aligned.m16n8k16.row.col.f32.f16.f16.f32 "
                 "{%0,%1,%2,%3},{%4,%5,%6,%7},{%8,%9},{%0,%1,%2,%3};"
                 : "+f"(d0), "+f"(d1), "+f"(d2), "+f"(d3)
                 : "r"(a0), "r"(a1), "r"(a2), "r"(a3), "r"(b0), "r"(b1));
}

// ============================ kernel 1: xe ============================
// g_xeh[c=b*32+h][e] = fp16( relu( inputs[b,e,:] @ W[:,h] + bias[h] ) )
__global__ __launch_bounds__(256) void xe_kernel(const float* __restrict__ inp,
                                                 const float* __restrict__ W,
                                                 const float* __restrict__ bias) {
    extern __shared__ float xs[];
    float* in_s = xs;                                  // [256 rows][64]
    int t = threadIdx.x, lane = t & 31, warp = t >> 5;
    float* ts = xs + XE_TS_OFF + warp * (32 * 33);
    int eBase = blockIdx.x * 64;
    uint32_t in_sb = smem_u32(in_s);

    float Wr[64];
#pragma unroll
    for (int d = 0; d < 64; d++) Wr[d] = W[d * 32 + lane];
    float bl = bias[lane];

    int bb  = warp >> 1;
    int elo = (warp & 1) * 32;

    for (int bg = 0; bg < 4; bg++) {
#pragma unroll
        for (int j = 0; j < 16; j++) {
            int id = t + j * 256;
            int row = id >> 4, q = id & 15;
            const float* src = inp + ((size_t)(bg * 4 + (row >> 6)) * E_DIM + eBase + (row & 63)) * 64 + q * 4;
            cpa16(in_sb + (uint32_t)(row * 64 + q * 4) * 4u, src);
        }
        CP_COMMIT();
        CP_WAIT(0);
        __syncthreads();

#pragma unroll 1
        for (int rr = 0; rr < 32; rr++) {
            const float4* row = reinterpret_cast<const float4*>(in_s + (bb * 64 + elo + rr) * 64);
            float a0 = bl, a1 = 0.f, a2 = 0.f, a3 = 0.f;
#pragma unroll
            for (int dq = 0; dq < 16; dq++) {
                float4 iv = row[dq];               // uniform -> LDS.128 broadcast
                a0 = fmaf(iv.x, Wr[4 * dq + 0], a0);
                a1 = fmaf(iv.y, Wr[4 * dq + 1], a1);
                a2 = fmaf(iv.z, Wr[4 * dq + 2], a2);
                a3 = fmaf(iv.w, Wr[4 * dq + 3], a3);
            }
            ts[lane * 33 + rr] = fmaxf((a0 + a1) + (a2 + a3), 0.f);
        }
        __syncwarp();
#pragma unroll
        for (int j = 0; j < 32; j++) {
            g_xeh[((size_t)((bg * 4 + bb) * 32 + j)) * E_DIM + eBase + elo + lane] =
                __float2half_rn(ts[j * 33 + lane]);
        }
        __syncthreads();
    }
}

// ============================ kernel 2: A build ============================
// g_ah[m][k] = fp16( w*inci + b ), pure streaming
__global__ __launch_bounds__(256) void abuild(const float* __restrict__ w,
                                              const float* __restrict__ inci,
                                              const float* __restrict__ b) {
    size_t base = ((size_t)blockIdx.x * 256 + threadIdx.x) * 8;
    float4 w0 = *reinterpret_cast<const float4*>(w + base);
    float4 w1 = *reinterpret_cast<const float4*>(w + base + 4);
    float4 i0 = *reinterpret_cast<const float4*>(inci + base);
    float4 i1 = *reinterpret_cast<const float4*>(inci + base + 4);
    float4 b0 = *reinterpret_cast<const float4*>(b + base);
    float4 b1 = *reinterpret_cast<const float4*>(b + base + 4);
    __half2 h0 = __floats2half2_rn(fmaf(w0.x, i0.x, b0.x), fmaf(w0.y, i0.y, b0.y));
    __half2 h1 = __floats2half2_rn(fmaf(w0.z, i0.z, b0.z), fmaf(w0.w, i0.w, b0.w));
    __half2 h2 = __floats2half2_rn(fmaf(w1.x, i1.x, b1.x), fmaf(w1.y, i1.y, b1.y));
    __half2 h3 = __floats2half2_rn(fmaf(w1.z, i1.z, b1.z), fmaf(w1.w, i1.w, b1.w));
    uint4 o;
    o.x = *reinterpret_cast<uint32_t*>(&h0);
    o.y = *reinterpret_cast<uint32_t*>(&h1);
    o.z = *reinterpret_cast<uint32_t*>(&h2);
    o.w = *reinterpret_cast<uint32_t*>(&h3);
    *reinterpret_cast<uint4*>(g_ah + base) = o;
}

// ============================ kernel 3: fp16 GEMM ============================
// g_part[sk][m][c] = sum_{k in slice} g_ah[m][k] * g_xeh[c][k]
__global__ __launch_bounds__(256, 1) void gemm_f16() {
    extern __shared__ char sm[];
    uint32_t sb = smem_u32(sm);
    int t = threadIdx.x, lane = t & 31, warp = t >> 5;
    int mBase = blockIdx.x * MT;
    int nBase = blockIdx.y * NT;
    size_t kBase = (size_t)blockIdx.z * KSLICE;

    // cp.async addressing
    int ar = t >> 1, ac = t & 1;
    const __half* gA = g_ah  + (size_t)(mBase + ar) * E_DIM + kBase + ac * 16;
    uint32_t aDst = sb + STG_A + (uint32_t)ar * A_ROWB + (uint32_t)ac * 32u;
    const __half* gB = g_xeh + (size_t)(nBase + t) * E_DIM + kBase;
    uint32_t bDst = sb + STG_B + (uint32_t)t * A_ROWB;

    float acc[4][8][4];
#pragma unroll
    for (int mi = 0; mi < 4; mi++)
#pragma unroll
        for (int nj = 0; nj < 8; nj++)
#pragma unroll
            for (int v = 0; v < 4; v++) acc[mi][nj][v] = 0.f;

#define LOAD_STAGE(s) do {                                                    \
    uint32_t so = (uint32_t)((s) % 3) * STG_BYTES;                            \
    const __half* pa = gA + (size_t)(s) * KC;                                 \
    cpa16(aDst + so, pa);                                                     \
    cpa16(aDst + so + 16u, pa + 8);                                           \
    const __half* pb = gB + (size_t)(s) * KC;                                 \
    _Pragma("unroll") for (int c = 0; c < 4; c++)                             \
        cpa16(bDst + so + c * 16u, pb + c * 8);                               \
    CP_COMMIT();                                                              \
} while (0)

    LOAD_STAGE(0);
    LOAD_STAGE(1);

    // ldmatrix lane base addresses (stride-80B rows -> conflict-free phases)
    int wm = warp & 1, wn = warp >> 1;
    uint32_t aAddr = sb + STG_A +
        (uint32_t)(wm * 64 + ((lane >> 3) & 1) * 8 + (lane & 7)) * A_ROWB + (uint32_t)(lane >> 4) * 16u;
    uint32_t bAddr = sb + STG_B +
        (uint32_t)(wn * 64 + (lane >> 4) * 8 + (lane & 7)) * A_ROWB + (uint32_t)((lane >> 3) & 1) * 16u;

    for (int s = 0; s < NSTG; s++) {
        CP_WAIT(1);
        __syncthreads();
        if (s + 2 < NSTG) LOAD_STAGE(s + 2); else CP_COMMIT();

        uint32_t so = (uint32_t)(s % 3) * STG_BYTES;
#pragma unroll
        for (int kk = 0; kk < 2; kk++) {
            uint32_t a[4][4], b[8][2];
#pragma unroll
            for (int mi = 0; mi < 4; mi++)
                ldmx4(a[mi][0], a[mi][1], a[mi][2], a[mi][3],
                      aAddr + so + (uint32_t)mi * 16u * A_ROWB + (uint32_t)kk * 32u);
#pragma unroll
            for (int nj4 = 0; nj4 < 4; nj4++)
                ldmx4(b[2 * nj4][0], b[2 * nj4][1], b[2 * nj4 + 1][0], b[2 * nj4 + 1][1],
                      bAddr + so + (uint32_t)nj4 * 16u * A_ROWB + (uint32_t)kk * 32u);
#pragma unroll
            for (int mi = 0; mi < 4; mi++)
#pragma unroll
                for (int nj = 0; nj < 8; nj++)
                    mma16816(acc[mi][nj][0], acc[mi][nj][1], acc[mi][nj][2], acc[mi][nj][3],
                             a[mi][0], a[mi][1], a[mi][2], a[mi][3],
                             b[nj][0], b[nj][1]);
        }
    }

    // epilogue: write split-K partials
    int lr = lane >> 2, lq = lane & 3;
#pragma unroll
    for (int mi = 0; mi < 4; mi++)
#pragma unroll
        for (int nj = 0; nj < 8; nj++) {
            int m = mBase + wm * 64 + mi * 16 + lr;
            int c = nBase + wn * 64 + nj * 8 + 2 * lq;
            float* p = g_part + ((size_t)blockIdx.z * N_NODES + m) * NCOL + c;
            *reinterpret_cast<float2*>(p) = make_float2(acc[mi][nj][0], acc[mi][nj][1]);
            *reinterpret_cast<float2*>(p + 8 * NCOL) = make_float2(acc[mi][nj][2], acc[mi][nj][3]);
        }
}

// ============================ kernel 4: reduce ============================
__global__ __launch_bounds__(256) void reduce_kernel(float* __restrict__ out) {
    int i = blockIdx.x * 256 + threadIdx.x;
    int pc = i * 4;
    int n = pc >> 9, c = pc & 511;
    float4 a = make_float4(0.f, 0.f, 0.f, 0.f);
#pragma unroll
    for (int s = 0; s < SPLITK; s++) {
        float4 v = *reinterpret_cast<const float4*>(g_part + ((size_t)s * N_NODES + n) * NCOL + c);
        a.x += v.x; a.y += v.y; a.z += v.z; a.w += v.w;
    }
    int b = c >> 5, h = c & 31;
    *reinterpret_cast<float4*>(out + ((size_t)b * N_NODES + n) * 32 + h) = a;
}

extern "C" void kernel_launch(void* const* d_in, const int* in_sizes, int n_in,
                              void* d_out, int out_size) {
    const float* inp  = (const float*)d_in[0];
    const float* W    = (const float*)d_in[1];
    const float* bias = (const float*)d_in[2];
    const float* inci = (const float*)d_in[3];
    const float* w    = (const float*)d_in[4];
    const float* b    = (const float*)d_in[5];
    float* out = (float*)d_out;

    cudaFuncSetAttribute(xe_kernel, cudaFuncAttributeMaxDynamicSharedMemorySize, XE_SMEM);
    cudaFuncSetAttribute(gemm_f16,  cudaFuncAttributeMaxDynamicSharedMemorySize, GEMM_SMEM);

    xe_kernel<<<E_DIM / 64, 256, XE_SMEM>>>(inp, W, bias);
    abuild<<<(N_NODES * E_DIM) / (8 * 256), 256>>>(w, inci, b);
    dim3 grid(N_NODES / MT, NCOL / NT, SPLITK);   // (16, 2, 4) = 128 CTAs
    gemm_f16<<<grid, 256, GEMM_SMEM>>>();
    reduce_kernel<<<(N_NODES * NCOL) / (4 * 256), 256>>>(out);
}